// round 1
// baseline (speedup 1.0000x reference)
#include <cuda_runtime.h>

#define N_NODES 20000
#define N_EDGES 320000
#define NODE_F  72     // 8 (l0) + 24 (l1) + 40 (l2) floats per node
#define NODE_F4 18     // in float4

// Scratch (device globals: no allocation allowed)
__device__ float4 g_xc[N_NODES * NODE_F4];  // packed node features x
__device__ float4 g_y [N_NODES * NODE_F4];  // aggregated messages y

// ---------------------------------------------------------------------------
// Kernel 1: pack x0/x1/x2 into compact [node][72] layout, zero y
// ---------------------------------------------------------------------------
__global__ void pack_kernel(const float4* __restrict__ x0,
                            const float4* __restrict__ x1,
                            const float4* __restrict__ x2)
{
    int i = blockIdx.x * blockDim.x + threadIdx.x;
    if (i >= N_NODES * NODE_F4) return;
    int node = i / NODE_F4;
    int k    = i - node * NODE_F4;
    float4 v;
    if (k < 2)      v = x0[node * 2  + k];
    else if (k < 8) v = x1[node * 6  + (k - 2)];
    else            v = x2[node * 10 + (k - 8)];
    g_xc[i] = v;
    g_y[i]  = make_float4(0.f, 0.f, 0.f, 0.f);
}

// ---------------------------------------------------------------------------
// Kernel 2: edge message passing  y[dst] += val * x[src]
// ---------------------------------------------------------------------------
__device__ __forceinline__ void red_add_v4(float* addr, float a, float b, float c, float d)
{
    asm volatile("red.global.add.v4.f32 [%0], {%1, %2, %3, %4};"
                 :: "l"(addr), "f"(a), "f"(b), "f"(c), "f"(d) : "memory");
}

__global__ void mp_kernel(const float* __restrict__ ev,
                          const int*   __restrict__ src,
                          const int*   __restrict__ dst)
{
    int i = blockIdx.x * blockDim.x + threadIdx.x;
    if (i >= N_EDGES * NODE_F4) return;
    int e = i / NODE_F4;
    int k = i - e * NODE_F4;
    int s = src[e];
    int t = dst[e];
    float v = ev[e];
    float4 xv = g_xc[s * NODE_F4 + k];
    red_add_v4((float*)&g_y[t * NODE_F4 + k], v * xv.x, v * xv.y, v * xv.z, v * xv.w);
}

// ---------------------------------------------------------------------------
// Kernel 3: fused CG products + SO(3) linear + residual, per node
// layout within a 72-float node vector: l0 @0 [c], l1 @8 [c*3+m], l2 @32 [c*5+m]
// ---------------------------------------------------------------------------
template<int L1, int L2, int L>
__device__ __forceinline__ void coupling(const float* __restrict__ A,
                                         const float* __restrict__ B,
                                         const float* __restrict__ W,
                                         int coff, int o, float* __restrict__ out)
{
    constexpr int N1 = 2 * L1 + 1;
    constexpr int N2 = 2 * L2 + 1;
    constexpr int OA = (L1 == 0) ? 0 : ((L1 == 1) ? 8 : 32);
    constexpr int OB = (L2 == 0) ? 0 : ((L2 == 1) ? 8 : 32);

    // local copies (smem -> regs)
    float Bl[8][N2];
#pragma unroll
    for (int d = 0; d < 8; d++)
#pragma unroll
        for (int q = 0; q < N2; q++) Bl[d][q] = B[OB + d * N2 + q];

    // T[p][q] = sum_d W[(coff + p*8 + d)*8 + o] * b[d][q]
    float T[8][N2];
    const float* Wp = W + coff * 8 + o;
#pragma unroll
    for (int p = 0; p < 8; p++) {
#pragma unroll
        for (int q = 0; q < N2; q++) T[p][q] = 0.f;
#pragma unroll
        for (int d = 0; d < 8; d++) {
            float wv = __ldg(Wp + (p * 8 + d) * 8);
#pragma unroll
            for (int q = 0; q < N2; q++) T[p][q] += wv * Bl[d][q];
        }
    }

    // S[p'][q'] = sum_p a[p][p'] * T[p][q']
    float S[N1][N2];
#pragma unroll
    for (int pp = 0; pp < N1; pp++)
#pragma unroll
        for (int q = 0; q < N2; q++) S[pp][q] = 0.f;
#pragma unroll
    for (int p = 0; p < 8; p++) {
#pragma unroll
        for (int pp = 0; pp < N1; pp++) {
            float av = A[OA + p * N1 + pp];
#pragma unroll
            for (int q = 0; q < N2; q++) S[pp][q] += av * T[p][q];
        }
    }

    // hardcoded sparse Clebsch-Gordan contraction: out[m] += CG[m,p',q'] S[p'][q']
    if constexpr (L1 == 0 && L2 == 0 && L == 0) {
        out[0] += S[0][0];
    } else if constexpr (L1 == 1 && L2 == 1 && L == 0) {
        out[0] += 0.57735027f * (S[0][2] - S[1][1] + S[2][0]);
    } else if constexpr (L1 == 2 && L2 == 2 && L == 0) {
        out[0] += 0.44721360f * (S[0][4] - S[1][3] + S[2][2] - S[3][1] + S[4][0]);
    } else if constexpr (L1 == 0 && L2 == 1 && L == 1) {
        out[0] += S[0][0]; out[1] += S[0][1]; out[2] += S[0][2];
    } else if constexpr (L1 == 1 && L2 == 0 && L == 1) {
        out[0] += S[0][0]; out[1] += S[1][0]; out[2] += S[2][0];
    } else if constexpr (L1 == 1 && L2 == 1 && L == 1) {
        out[0] += 0.70710678f * (S[1][0] - S[0][1]);
        out[1] += 0.70710678f * (S[2][0] - S[0][2]);
        out[2] += 0.70710678f * (S[2][1] - S[1][2]);
    } else if constexpr (L1 == 1 && L2 == 2 && L == 1) {
        out[0] += 0.31622777f * S[0][2] - 0.54772256f * S[1][1] + 0.77459667f * S[2][0];
        out[1] += 0.54772256f * S[0][3] - 0.63245553f * S[1][2] + 0.54772256f * S[2][1];
        out[2] += 0.77459667f * S[0][4] - 0.54772256f * S[1][3] + 0.31622777f * S[2][2];
    } else if constexpr (L1 == 2 && L2 == 1 && L == 1) {
        out[0] += 0.77459667f * S[0][2] - 0.54772256f * S[1][1] + 0.31622777f * S[2][0];
        out[1] += 0.54772256f * S[1][2] - 0.63245553f * S[2][1] + 0.54772256f * S[3][0];
        out[2] += 0.31622777f * S[2][2] - 0.54772256f * S[3][1] + 0.77459667f * S[4][0];
    } else if constexpr (L1 == 2 && L2 == 2 && L == 1) {
        out[0] += -0.44721360f * S[0][3] + 0.54772256f * S[1][2] - 0.54772256f * S[2][1] + 0.44721360f * S[3][0];
        out[1] += -0.63245553f * S[0][4] + 0.31622777f * S[1][3] - 0.31622777f * S[3][1] + 0.63245553f * S[4][0];
        out[2] += -0.44721360f * S[1][4] + 0.54772256f * S[2][3] - 0.54772256f * S[3][2] + 0.44721360f * S[4][1];
    } else if constexpr (L1 == 0 && L2 == 2 && L == 2) {
        out[0] += S[0][0]; out[1] += S[0][1]; out[2] += S[0][2]; out[3] += S[0][3]; out[4] += S[0][4];
    } else if constexpr (L1 == 2 && L2 == 0 && L == 2) {
        out[0] += S[0][0]; out[1] += S[1][0]; out[2] += S[2][0]; out[3] += S[3][0]; out[4] += S[4][0];
    } else if constexpr (L1 == 1 && L2 == 1 && L == 2) {
        out[0] += S[0][0];
        out[1] += 0.70710678f * (S[0][1] + S[1][0]);
        out[2] += 0.40824829f * (S[0][2] + S[2][0]) + 0.81649658f * S[1][1];
        out[3] += 0.70710678f * (S[1][2] + S[2][1]);
        out[4] += S[2][2];
    } else if constexpr (L1 == 1 && L2 == 2 && L == 2) {
        out[0] += 0.81649658f * S[1][0] - 0.57735027f * S[0][1];
        out[1] += 0.57735027f * S[2][0] + 0.40824829f * S[1][1] - 0.70710678f * S[0][2];
        out[2] += 0.70710678f * (S[2][1] - S[0][3]);
        out[3] += 0.70710678f * S[2][2] - 0.40824829f * S[1][3] - 0.57735027f * S[0][4];
        out[4] += 0.57735027f * S[2][3] - 0.81649658f * S[1][4];
    } else if constexpr (L1 == 2 && L2 == 1 && L == 2) {
        out[0] += 0.57735027f * S[1][0] - 0.81649658f * S[0][1];
        out[1] += 0.70710678f * S[2][0] - 0.40824829f * S[1][1] - 0.57735027f * S[0][2];
        out[2] += 0.70710678f * (S[3][0] - S[1][2]);
        out[3] += 0.57735027f * S[4][0] + 0.40824829f * S[3][1] - 0.70710678f * S[2][2];
        out[4] += 0.81649658f * S[4][1] - 0.57735027f * S[3][2];
    } else if constexpr (L1 == 2 && L2 == 2 && L == 2) {
        out[0] += 0.53452248f * (S[0][2] + S[2][0]) - 0.65465367f * S[1][1];
        out[1] += 0.65465367f * (S[0][3] + S[3][0]) - 0.26726124f * (S[1][2] + S[2][1]);
        out[2] += 0.53452248f * (S[0][4] + S[4][0]) + 0.26726124f * (S[1][3] + S[3][1]) - 0.53452248f * S[2][2];
        out[3] += 0.65465367f * (S[1][4] + S[4][1]) - 0.26726124f * (S[2][3] + S[3][2]);
        out[4] += 0.53452248f * (S[2][4] + S[4][2]) - 0.65465367f * S[3][3];
    }
}

__device__ __forceinline__ void product(const float* __restrict__ A,
                                        const float* __restrict__ B,
                                        const float* __restrict__ W0,
                                        const float* __restrict__ W1,
                                        const float* __restrict__ W2,
                                        int o, float* o0, float* o1, float* o2)
{
    // l = 0
    coupling<0, 0, 0>(A, B, W0,   0, o, o0);
    coupling<1, 1, 0>(A, B, W0,  64, o, o0);
    coupling<2, 2, 0>(A, B, W0, 128, o, o0);
    // l = 1
    coupling<0, 1, 1>(A, B, W1,   0, o, o1);
    coupling<1, 0, 1>(A, B, W1,  64, o, o1);
    coupling<1, 1, 1>(A, B, W1, 128, o, o1);
    coupling<1, 2, 1>(A, B, W1, 192, o, o1);
    coupling<2, 1, 1>(A, B, W1, 256, o, o1);
    coupling<2, 2, 1>(A, B, W1, 320, o, o1);
    // l = 2
    coupling<0, 2, 2>(A, B, W2,   0, o, o2);
    coupling<1, 1, 2>(A, B, W2,  64, o, o2);
    coupling<1, 2, 2>(A, B, W2, 128, o, o2);
    coupling<2, 0, 2>(A, B, W2, 192, o, o2);
    coupling<2, 1, 2>(A, B, W2, 256, o, o2);
    coupling<2, 2, 2>(A, B, W2, 320, o, o2);
}

__global__ void __launch_bounds__(256)
node_kernel(const float* __restrict__ w_mm0, const float* __restrict__ w_mm1, const float* __restrict__ w_mm2,
            const float* __restrict__ w_mi0, const float* __restrict__ w_mi1, const float* __restrict__ w_mi2,
            const float* __restrict__ w_ii0, const float* __restrict__ w_ii1, const float* __restrict__ w_ii2,
            float* __restrict__ out)
{
    __shared__ float sx[32][NODE_F];
    __shared__ float sy[32][NODE_F];

    int tid  = threadIdx.x;
    int base = blockIdx.x * 32;

    const float4* xc = g_xc + base * NODE_F4;
    const float4* yv = g_y  + base * NODE_F4;
    float4* sx4 = (float4*)&sx[0][0];
    float4* sy4 = (float4*)&sy[0][0];
#pragma unroll
    for (int i = tid; i < 32 * NODE_F4; i += 256) {
        sx4[i] = xc[i];
        sy4[i] = yv[i];
    }
    __syncthreads();

    int nl = tid >> 3;   // local node 0..31
    int o  = tid & 7;    // output channel 0..7
    const float* X = sx[nl];
    const float* Y = sy[nl];

    float o0[1] = {0.f};
    float o1[3] = {0.f, 0.f, 0.f};
    float o2[5] = {0.f, 0.f, 0.f, 0.f, 0.f};

    product(Y, Y, w_mm0, w_mm1, w_mm2, o, o0, o1, o2);  // y_mp_mp
    product(Y, X, w_mi0, w_mi1, w_mi2, o, o0, o1, o2);  // y_mp_id
    product(X, X, w_ii0, w_ii1, w_ii2, o, o0, o1, o2);  // y_id_id

    int n = base + nl;
    // output: [x0' (20000*8) | x1' (20000*24) | x2' (20000*40)], residual added
    out[n * 8 + o] = o0[0] + X[o];
#pragma unroll
    for (int m = 0; m < 3; m++)
        out[160000 + n * 24 + o * 3 + m] = o1[m] + X[8 + o * 3 + m];
#pragma unroll
    for (int m = 0; m < 5; m++)
        out[640000 + n * 40 + o * 5 + m] = o2[m] + X[32 + o * 5 + m];
}

// ---------------------------------------------------------------------------
// launch
// input order (setup_inputs dict order):
// 0:x0 1:x1 2:x2 3:edge_vals 4:edge_src 5:edge_dst
// 6..8: w_mpmp0..2  9..11: w_mpid0..2  12..14: w_idid0..2
// ---------------------------------------------------------------------------
extern "C" void kernel_launch(void* const* d_in, const int* in_sizes, int n_in,
                              void* d_out, int out_size)
{
    const float4* x0 = (const float4*)d_in[0];
    const float4* x1 = (const float4*)d_in[1];
    const float4* x2 = (const float4*)d_in[2];
    const float*  ev = (const float*)d_in[3];
    const int*   src = (const int*)d_in[4];
    const int*   dst = (const int*)d_in[5];

    const float* w_mm0 = (const float*)d_in[6];
    const float* w_mm1 = (const float*)d_in[7];
    const float* w_mm2 = (const float*)d_in[8];
    const float* w_mi0 = (const float*)d_in[9];
    const float* w_mi1 = (const float*)d_in[10];
    const float* w_mi2 = (const float*)d_in[11];
    const float* w_ii0 = (const float*)d_in[12];
    const float* w_ii1 = (const float*)d_in[13];
    const float* w_ii2 = (const float*)d_in[14];

    float* out = (float*)d_out;

    {
        int total = N_NODES * NODE_F4;
        pack_kernel<<<(total + 255) / 256, 256>>>(x0, x1, x2);
    }
    {
        int total = N_EDGES * NODE_F4;
        mp_kernel<<<(total + 255) / 256, 256>>>(ev, src, dst);
    }
    node_kernel<<<N_NODES / 32, 256>>>(w_mm0, w_mm1, w_mm2,
                                       w_mi0, w_mi1, w_mi2,
                                       w_ii0, w_ii1, w_ii2, out);
}

// round 2
// speedup vs baseline: 1.0167x; 1.0167x over previous
#include <cuda_runtime.h>

#define N_NODES 20000
#define N_EDGES 320000
#define NODE_F  72     // 8 (l0) + 24 (l1) + 40 (l2) floats per node
#define NODE_F4 18     // in float4

// Scratch (device globals: no allocation allowed)
__device__ float4 g_xc[N_NODES * NODE_F4];  // packed node features x
__device__ float4 g_y [N_NODES * NODE_F4];  // aggregated messages y

// ---------------------------------------------------------------------------
// Kernel 1: pack x0/x1/x2 into compact [node][72] layout, zero y
// ---------------------------------------------------------------------------
__global__ void pack_kernel(const float4* __restrict__ x0,
                            const float4* __restrict__ x1,
                            const float4* __restrict__ x2)
{
    int i = blockIdx.x * blockDim.x + threadIdx.x;
    if (i >= N_NODES * NODE_F4) return;
    int node = i / NODE_F4;
    int k    = i - node * NODE_F4;
    float4 v;
    if (k < 2)      v = x0[node * 2  + k];
    else if (k < 8) v = x1[node * 6  + (k - 2)];
    else            v = x2[node * 10 + (k - 8)];
    g_xc[i] = v;
    g_y[i]  = make_float4(0.f, 0.f, 0.f, 0.f);
}

// ---------------------------------------------------------------------------
// Kernel 2: edge message passing  y[dst] += val * x[src]
// ---------------------------------------------------------------------------
__device__ __forceinline__ void red_add_v4(float* addr, float a, float b, float c, float d)
{
    asm volatile("red.global.add.v4.f32 [%0], {%1, %2, %3, %4};"
                 :: "l"(addr), "f"(a), "f"(b), "f"(c), "f"(d) : "memory");
}

__global__ void mp_kernel(const float* __restrict__ ev,
                          const int*   __restrict__ src,
                          const int*   __restrict__ dst)
{
    int i = blockIdx.x * blockDim.x + threadIdx.x;
    if (i >= N_EDGES * NODE_F4) return;
    int e = i / NODE_F4;
    int k = i - e * NODE_F4;
    int s = src[e];
    int t = dst[e];
    float v = ev[e];
    float4 xv = g_xc[s * NODE_F4 + k];
    red_add_v4((float*)&g_y[t * NODE_F4 + k], v * xv.x, v * xv.y, v * xv.z, v * xv.w);
}

// ---------------------------------------------------------------------------
// Kernel 3: fused CG products + SO(3) linear + residual, per node
// layout within a 72-float node vector: l0 @0 [c], l1 @8 [c*3+m], l2 @32 [c*5+m]
// ---------------------------------------------------------------------------
template<int L1, int L2, int L>
__device__ __forceinline__ void coupling(const float* __restrict__ A,
                                         const float* __restrict__ B,
                                         const float* __restrict__ W,
                                         int coff, int o, float* __restrict__ out)
{
    constexpr int N1 = 2 * L1 + 1;
    constexpr int N2 = 2 * L2 + 1;
    constexpr int OA = (L1 == 0) ? 0 : ((L1 == 1) ? 8 : 32);
    constexpr int OB = (L2 == 0) ? 0 : ((L2 == 1) ? 8 : 32);

    // local copies (smem -> regs)
    float Bl[8][N2];
#pragma unroll
    for (int d = 0; d < 8; d++)
#pragma unroll
        for (int q = 0; q < N2; q++) Bl[d][q] = B[OB + d * N2 + q];

    // T[p][q] = sum_d W[(coff + p*8 + d)*8 + o] * b[d][q]
    float T[8][N2];
    const float* Wp = W + coff * 8 + o;
#pragma unroll
    for (int p = 0; p < 8; p++) {
#pragma unroll
        for (int q = 0; q < N2; q++) T[p][q] = 0.f;
#pragma unroll
        for (int d = 0; d < 8; d++) {
            float wv = __ldg(Wp + (p * 8 + d) * 8);
#pragma unroll
            for (int q = 0; q < N2; q++) T[p][q] += wv * Bl[d][q];
        }
    }

    // S[p'][q'] = sum_p a[p][p'] * T[p][q']
    float S[N1][N2];
#pragma unroll
    for (int pp = 0; pp < N1; pp++)
#pragma unroll
        for (int q = 0; q < N2; q++) S[pp][q] = 0.f;
#pragma unroll
    for (int p = 0; p < 8; p++) {
#pragma unroll
        for (int pp = 0; pp < N1; pp++) {
            float av = A[OA + p * N1 + pp];
#pragma unroll
            for (int q = 0; q < N2; q++) S[pp][q] += av * T[p][q];
        }
    }

    // hardcoded sparse Clebsch-Gordan contraction: out[m] += CG[m,p',q'] S[p'][q']
    if constexpr (L1 == 0 && L2 == 0 && L == 0) {
        out[0] += S[0][0];
    } else if constexpr (L1 == 1 && L2 == 1 && L == 0) {
        out[0] += 0.57735027f * (S[0][2] - S[1][1] + S[2][0]);
    } else if constexpr (L1 == 2 && L2 == 2 && L == 0) {
        out[0] += 0.44721360f * (S[0][4] - S[1][3] + S[2][2] - S[3][1] + S[4][0]);
    } else if constexpr (L1 == 0 && L2 == 1 && L == 1) {
        out[0] += S[0][0]; out[1] += S[0][1]; out[2] += S[0][2];
    } else if constexpr (L1 == 1 && L2 == 0 && L == 1) {
        out[0] += S[0][0]; out[1] += S[1][0]; out[2] += S[2][0];
    } else if constexpr (L1 == 1 && L2 == 1 && L == 1) {
        out[0] += 0.70710678f * (S[1][0] - S[0][1]);
        out[1] += 0.70710678f * (S[2][0] - S[0][2]);
        out[2] += 0.70710678f * (S[2][1] - S[1][2]);
    } else if constexpr (L1 == 1 && L2 == 2 && L == 1) {
        out[0] += 0.31622777f * S[0][2] - 0.54772256f * S[1][1] + 0.77459667f * S[2][0];
        out[1] += 0.54772256f * S[0][3] - 0.63245553f * S[1][2] + 0.54772256f * S[2][1];
        out[2] += 0.77459667f * S[0][4] - 0.54772256f * S[1][3] + 0.31622777f * S[2][2];
    } else if constexpr (L1 == 2 && L2 == 1 && L == 1) {
        out[0] += 0.77459667f * S[0][2] - 0.54772256f * S[1][1] + 0.31622777f * S[2][0];
        out[1] += 0.54772256f * S[1][2] - 0.63245553f * S[2][1] + 0.54772256f * S[3][0];
        out[2] += 0.31622777f * S[2][2] - 0.54772256f * S[3][1] + 0.77459667f * S[4][0];
    } else if constexpr (L1 == 2 && L2 == 2 && L == 1) {
        out[0] += -0.44721360f * S[0][3] + 0.54772256f * S[1][2] - 0.54772256f * S[2][1] + 0.44721360f * S[3][0];
        out[1] += -0.63245553f * S[0][4] + 0.31622777f * S[1][3] - 0.31622777f * S[3][1] + 0.63245553f * S[4][0];
        out[2] += -0.44721360f * S[1][4] + 0.54772256f * S[2][3] - 0.54772256f * S[3][2] + 0.44721360f * S[4][1];
    } else if constexpr (L1 == 0 && L2 == 2 && L == 2) {
        out[0] += S[0][0]; out[1] += S[0][1]; out[2] += S[0][2]; out[3] += S[0][3]; out[4] += S[0][4];
    } else if constexpr (L1 == 2 && L2 == 0 && L == 2) {
        out[0] += S[0][0]; out[1] += S[1][0]; out[2] += S[2][0]; out[3] += S[3][0]; out[4] += S[4][0];
    } else if constexpr (L1 == 1 && L2 == 1 && L == 2) {
        out[0] += S[0][0];
        out[1] += 0.70710678f * (S[0][1] + S[1][0]);
        out[2] += 0.40824829f * (S[0][2] + S[2][0]) + 0.81649658f * S[1][1];
        out[3] += 0.70710678f * (S[1][2] + S[2][1]);
        out[4] += S[2][2];
    } else if constexpr (L1 == 1 && L2 == 2 && L == 2) {
        out[0] += 0.81649658f * S[1][0] - 0.57735027f * S[0][1];
        out[1] += 0.57735027f * S[2][0] + 0.40824829f * S[1][1] - 0.70710678f * S[0][2];
        out[2] += 0.70710678f * (S[2][1] - S[0][3]);
        out[3] += 0.70710678f * S[2][2] - 0.40824829f * S[1][3] - 0.57735027f * S[0][4];
        out[4] += 0.57735027f * S[2][3] - 0.81649658f * S[1][4];
    } else if constexpr (L1 == 2 && L2 == 1 && L == 2) {
        out[0] += 0.57735027f * S[1][0] - 0.81649658f * S[0][1];
        out[1] += 0.70710678f * S[2][0] - 0.40824829f * S[1][1] - 0.57735027f * S[0][2];
        out[2] += 0.70710678f * (S[3][0] - S[1][2]);
        out[3] += 0.57735027f * S[4][0] + 0.40824829f * S[3][1] - 0.70710678f * S[2][2];
        out[4] += 0.81649658f * S[4][1] - 0.57735027f * S[3][2];
    } else if constexpr (L1 == 2 && L2 == 2 && L == 2) {
        out[0] += 0.53452248f * (S[0][2] + S[2][0]) - 0.65465367f * S[1][1];
        out[1] += 0.65465367f * (S[0][3] + S[3][0]) - 0.26726124f * (S[1][2] + S[2][1]);
        out[2] += 0.53452248f * (S[0][4] + S[4][0]) + 0.26726124f * (S[1][3] + S[3][1]) - 0.53452248f * S[2][2];
        out[3] += 0.65465367f * (S[1][4] + S[4][1]) - 0.26726124f * (S[2][3] + S[3][2]);
        out[4] += 0.53452248f * (S[2][4] + S[4][2]) - 0.65465367f * S[3][3];
    }
}

__device__ __forceinline__ void product(const float* __restrict__ A,
                                        const float* __restrict__ B,
                                        const float* __restrict__ W0,
                                        const float* __restrict__ W1,
                                        const float* __restrict__ W2,
                                        int o, float* o0, float* o1, float* o2)
{
    // l = 0
    coupling<0, 0, 0>(A, B, W0,   0, o, o0);
    coupling<1, 1, 0>(A, B, W0,  64, o, o0);
    coupling<2, 2, 0>(A, B, W0, 128, o, o0);
    // l = 1
    coupling<0, 1, 1>(A, B, W1,   0, o, o1);
    coupling<1, 0, 1>(A, B, W1,  64, o, o1);
    coupling<1, 1, 1>(A, B, W1, 128, o, o1);
    coupling<1, 2, 1>(A, B, W1, 192, o, o1);
    coupling<2, 1, 1>(A, B, W1, 256, o, o1);
    coupling<2, 2, 1>(A, B, W1, 320, o, o1);
    // l = 2
    coupling<0, 2, 2>(A, B, W2,   0, o, o2);
    coupling<1, 1, 2>(A, B, W2,  64, o, o2);
    coupling<1, 2, 2>(A, B, W2, 128, o, o2);
    coupling<2, 0, 2>(A, B, W2, 192, o, o2);
    coupling<2, 1, 2>(A, B, W2, 256, o, o2);
    coupling<2, 2, 2>(A, B, W2, 320, o, o2);
}

__global__ void __launch_bounds__(256)
node_kernel(const float* __restrict__ w_mm0, const float* __restrict__ w_mm1, const float* __restrict__ w_mm2,
            const float* __restrict__ w_mi0, const float* __restrict__ w_mi1, const float* __restrict__ w_mi2,
            const float* __restrict__ w_ii0, const float* __restrict__ w_ii1, const float* __restrict__ w_ii2,
            float* __restrict__ out)
{
    __shared__ float sx[32][NODE_F];
    __shared__ float sy[32][NODE_F];

    int tid  = threadIdx.x;
    int base = blockIdx.x * 32;

    const float4* xc = g_xc + base * NODE_F4;
    const float4* yv = g_y  + base * NODE_F4;
    float4* sx4 = (float4*)&sx[0][0];
    float4* sy4 = (float4*)&sy[0][0];
#pragma unroll
    for (int i = tid; i < 32 * NODE_F4; i += 256) {
        sx4[i] = xc[i];
        sy4[i] = yv[i];
    }
    __syncthreads();

    int nl = tid >> 3;   // local node 0..31
    int o  = tid & 7;    // output channel 0..7
    const float* X = sx[nl];
    const float* Y = sy[nl];

    float o0[1] = {0.f};
    float o1[3] = {0.f, 0.f, 0.f};
    float o2[5] = {0.f, 0.f, 0.f, 0.f, 0.f};

    product(Y, Y, w_mm0, w_mm1, w_mm2, o, o0, o1, o2);  // y_mp_mp
    product(Y, X, w_mi0, w_mi1, w_mi2, o, o0, o1, o2);  // y_mp_id
    product(X, X, w_ii0, w_ii1, w_ii2, o, o0, o1, o2);  // y_id_id

    int n = base + nl;
    // output: [x0' (20000*8) | x1' (20000*24) | x2' (20000*40)], residual added
    out[n * 8 + o] = o0[0] + X[o];
#pragma unroll
    for (int m = 0; m < 3; m++)
        out[160000 + n * 24 + o * 3 + m] = o1[m] + X[8 + o * 3 + m];
#pragma unroll
    for (int m = 0; m < 5; m++)
        out[640000 + n * 40 + o * 5 + m] = o2[m] + X[32 + o * 5 + m];
}

// ---------------------------------------------------------------------------
// launch
// input order (setup_inputs dict order):
// 0:x0 1:x1 2:x2 3:edge_vals 4:edge_src 5:edge_dst
// 6..8: w_mpmp0..2  9..11: w_mpid0..2  12..14: w_idid0..2
// ---------------------------------------------------------------------------
extern "C" void kernel_launch(void* const* d_in, const int* in_sizes, int n_in,
                              void* d_out, int out_size)
{
    const float4* x0 = (const float4*)d_in[0];
    const float4* x1 = (const float4*)d_in[1];
    const float4* x2 = (const float4*)d_in[2];
    const float*  ev = (const float*)d_in[3];
    const int*   src = (const int*)d_in[4];
    const int*   dst = (const int*)d_in[5];

    const float* w_mm0 = (const float*)d_in[6];
    const float* w_mm1 = (const float*)d_in[7];
    const float* w_mm2 = (const float*)d_in[8];
    const float* w_mi0 = (const float*)d_in[9];
    const float* w_mi1 = (const float*)d_in[10];
    const float* w_mi2 = (const float*)d_in[11];
    const float* w_ii0 = (const float*)d_in[12];
    const float* w_ii1 = (const float*)d_in[13];
    const float* w_ii2 = (const float*)d_in[14];

    float* out = (float*)d_out;

    {
        int total = N_NODES * NODE_F4;
        pack_kernel<<<(total + 255) / 256, 256>>>(x0, x1, x2);
    }
    {
        int total = N_EDGES * NODE_F4;
        mp_kernel<<<(total + 255) / 256, 256>>>(ev, src, dst);
    }
    node_kernel<<<N_NODES / 32, 256>>>(w_mm0, w_mm1, w_mm2,
                                       w_mi0, w_mi1, w_mi2,
                                       w_ii0, w_ii1, w_ii2, out);
}